// round 1
// baseline (speedup 1.0000x reference)
#include <cuda_runtime.h>
#include <cstdint>
#include <cstddef>

// Problem constants (fixed shapes from reference)
#define BATCH 2
#define CH    128
#define NI    16            // inter channels
#define DD    16
#define HH    24
#define WW    24
#define NN    (DD*HH*WW)    // 9216 voxels
#define LOG2E 1.4426950408889634f

#define QT      128         // queries per block
#define KT      128         // keys per smem tile
#define GR      4           // key groups per block
#define THREADS (GR*128)
#define NTILES  (NN/KT)     // 72  (divisible by GR=4 -> 18 tiles/group)

typedef unsigned long long u64;

// scratch: q (pre-scaled by log2e), k, v, each [B][N][16] row-major per voxel
__device__ float g_qkv[3][BATCH*NN*NI];

// ---------------- f32x2 helpers (FFMA2: 2x fp32 throughput, PTX-only) ----------
__device__ __forceinline__ u64 ffma2(u64 a, u64 b, u64 c) {
    u64 d;
    asm("fma.rn.f32x2 %0, %1, %2, %3;" : "=l"(d) : "l"(a), "l"(b), "l"(c));
    return d;
}
__device__ __forceinline__ u64 pack2(float x, float y) {
    u64 r; asm("mov.b64 %0, {%1, %2};" : "=l"(r) : "f"(x), "f"(y)); return r;
}
__device__ __forceinline__ float2 unpack2(u64 a) {
    float2 r; asm("mov.b64 {%0, %1}, %2;" : "=f"(r.x), "=f"(r.y) : "l"(a)); return r;
}
__device__ __forceinline__ float ex2f(float x) {
    float r; asm("ex2.approx.f32 %0, %1;" : "=f"(r) : "f"(x)); return r;
}

// ---------------- Kernel 1: QKV projection (1x1x1 conv) ------------------------
// grid.x covers B*N voxels, grid.y = which matrix (0=q,1=k,2=v)
__global__ void qkv_kernel(const float* __restrict__ x,
                           const float* __restrict__ Wq, const float* __restrict__ bq,
                           const float* __restrict__ Wk, const float* __restrict__ bk,
                           const float* __restrict__ Wv, const float* __restrict__ bv) {
    __shared__ float sw[CH*NI];   // sw[c*16+i] = W[i][c]  (transposed for contiguous i)
    __shared__ float sb[NI];

    const int which = blockIdx.y;
    const float* W   = (which == 0) ? Wq : (which == 1) ? Wk : Wv;
    const float* bia = (which == 0) ? bq : (which == 1) ? bk : bv;

    for (int t = threadIdx.x; t < CH*NI; t += blockDim.x) {
        int c = t >> 4, i = t & 15;
        sw[t] = W[i*CH + c];
    }
    if (threadIdx.x < NI) sb[threadIdx.x] = bia[threadIdx.x];
    __syncthreads();

    const int idx = blockIdx.x * blockDim.x + threadIdx.x;   // b*N + n
    if (idx >= BATCH*NN) return;
    const int b = idx / NN;
    const int n = idx - b*NN;

    float acc[NI];
#pragma unroll
    for (int i = 0; i < NI; i++) acc[i] = sb[i];

    const float* xp = x + (size_t)b*CH*NN + n;
#pragma unroll 4
    for (int c = 0; c < CH; c++) {
        float xv = xp[(size_t)c*NN];
        const float4* wr = (const float4*)(sw + c*NI);
        float4 wa = wr[0], wb = wr[1], wc4 = wr[2], wd = wr[3];
        acc[0]  += wa.x*xv;  acc[1]  += wa.y*xv;  acc[2]  += wa.z*xv;  acc[3]  += wa.w*xv;
        acc[4]  += wb.x*xv;  acc[5]  += wb.y*xv;  acc[6]  += wb.z*xv;  acc[7]  += wb.w*xv;
        acc[8]  += wc4.x*xv; acc[9]  += wc4.y*xv; acc[10] += wc4.z*xv; acc[11] += wc4.w*xv;
        acc[12] += wd.x*xv;  acc[13] += wd.y*xv;  acc[14] += wd.z*xv;  acc[15] += wd.w*xv;
    }

    const float scale = (which == 0) ? LOG2E : 1.0f;  // fold log2(e) into q -> ex2 in attn
    float4* dst = (float4*)(g_qkv[which] + (size_t)idx*NI);
    dst[0] = make_float4(acc[0]*scale,  acc[1]*scale,  acc[2]*scale,  acc[3]*scale);
    dst[1] = make_float4(acc[4]*scale,  acc[5]*scale,  acc[6]*scale,  acc[7]*scale);
    dst[2] = make_float4(acc[8]*scale,  acc[9]*scale,  acc[10]*scale, acc[11]*scale);
    dst[3] = make_float4(acc[12]*scale, acc[13]*scale, acc[14]*scale, acc[15]*scale);
}

// ---------------- Kernel 2: streaming attention + out-proj + residual ----------
// grid = (NN/QT, BATCH), block = 512 threads = 4 key-groups x 128 query-threads.
// No max-subtraction (logits bounded << 88) -> partials additive across groups.
// smem floats: kbuf GR*KT*16 | vbuf GR*KT*16 | swo 2048 | sbo 128 | sred GR*QT*17
#define SRED_STRIDE 17
#define SMEM_FLOATS (GR*KT*NI + GR*KT*NI + CH*NI + CH + GR*QT*SRED_STRIDE)
#define SMEM_BYTES  (SMEM_FLOATS * 4)

__global__ void __launch_bounds__(THREADS, 1)
attn_kernel(const float* __restrict__ x,
            const float* __restrict__ Wo, const float* __restrict__ bo,
            const float* __restrict__ gamma, float* __restrict__ out) {
    extern __shared__ float smem[];
    float* kbuf = smem;                       // GR*KT*NI
    float* vbuf = kbuf + GR*KT*NI;            // GR*KT*NI
    float* swo  = vbuf + GR*KT*NI;            // CH*NI  (Wo is [C][I] row-major already)
    float* sbo  = swo + CH*NI;                // CH
    float* sred = sbo + CH;                   // GR*QT*17

    const int tid = threadIdx.x;
    const int g   = tid >> 7;        // key group 0..3
    const int lt  = tid & 127;       // query lane within block
    const int b   = blockIdx.y;
    const int q0  = blockIdx.x * QT;
    const int n   = q0 + lt;         // my query index

    for (int t = tid; t < CH*NI; t += THREADS) swo[t] = Wo[t];
    if (tid < CH) sbo[tid] = bo[tid];

    // my query vector (already * log2e), packed as 8x f32x2
    u64 qq[8];
    {
        const ulonglong2* qp = (const ulonglong2*)(g_qkv[0] + (size_t)(b*NN + n)*NI);
#pragma unroll
        for (int j = 0; j < 4; j++) { ulonglong2 t2 = qp[j]; qq[2*j] = t2.x; qq[2*j+1] = t2.y; }
    }

    u64 a2[8];
#pragma unroll
    for (int j = 0; j < 8; j++) a2[j] = 0ull;
    float lsum = 0.0f;

    const float4* kg = (const float4*)(g_qkv[1] + (size_t)b*NN*NI);
    const float4* vg = (const float4*)(g_qkv[2] + (size_t)b*NN*NI);
    float4* myk = (float4*)(kbuf + g*KT*NI);
    float4* myv = (float4*)(vbuf + g*KT*NI);
    const u64* krow = (const u64*)(kbuf + g*KT*NI);
    const u64* vrow = (const u64*)(vbuf + g*KT*NI);

    for (int t = g; t < NTILES; t += GR) {     // 18 tiles per group, uniform count
        const int m0 = t * KT;
        __syncthreads();                        // previous tile consumed by all groups
#pragma unroll
        for (int j = 0; j < 4; j++) {           // cooperative coalesced tile load
            int e = lt + j*128;                 // 512 float4 per tile
            myk[e] = kg[(size_t)m0*4 + e];
            myv[e] = vg[(size_t)m0*4 + e];
        }
        __syncthreads();

#pragma unroll 2
        for (int m = 0; m < KT; m++) {
            const ulonglong2* km = (const ulonglong2*)(krow + (size_t)m*8);
            ulonglong2 ka = km[0], kb = km[1], kc = km[2], kd = km[3];
            u64 d0 = 0ull, d1 = 0ull;
            d0 = ffma2(qq[0], ka.x, d0);  d1 = ffma2(qq[1], ka.y, d1);
            d0 = ffma2(qq[2], kb.x, d0);  d1 = ffma2(qq[3], kb.y, d1);
            d0 = ffma2(qq[4], kc.x, d0);  d1 = ffma2(qq[5], kc.y, d1);
            d0 = ffma2(qq[6], kd.x, d0);  d1 = ffma2(qq[7], kd.y, d1);
            float2 e0 = unpack2(d0), e1 = unpack2(d1);
            float s = (e0.x + e0.y) + (e1.x + e1.y);   // log2-scaled logit
            float p = ex2f(s);
            lsum += p;
            u64 pp = pack2(p, p);
            const ulonglong2* vm = (const ulonglong2*)(vrow + (size_t)m*8);
            ulonglong2 va = vm[0], vb = vm[1], vc = vm[2], vd = vm[3];
            a2[0] = ffma2(pp, va.x, a2[0]);  a2[1] = ffma2(pp, va.y, a2[1]);
            a2[2] = ffma2(pp, vb.x, a2[2]);  a2[3] = ffma2(pp, vb.y, a2[3]);
            a2[4] = ffma2(pp, vc.x, a2[4]);  a2[5] = ffma2(pp, vc.y, a2[5]);
            a2[6] = ffma2(pp, vd.x, a2[6]);  a2[7] = ffma2(pp, vd.y, a2[7]);
        }
    }

    // write per-group partials (additive: no running max)
    {
        float* pr = sred + (size_t)(g*QT + lt) * SRED_STRIDE;
#pragma unroll
        for (int j = 0; j < 8; j++) {
            float2 e = unpack2(a2[j]);
            pr[2*j] = e.x; pr[2*j+1] = e.y;
        }
        pr[16] = lsum;
    }
    __syncthreads();

    // merge 4 partials; thread (g,lt): query lt, channels [g*32, g*32+32)
    float o[NI]; float L = 0.0f;
#pragma unroll
    for (int i = 0; i < NI; i++) o[i] = 0.0f;
#pragma unroll
    for (int gg = 0; gg < GR; gg++) {
        const float* r = sred + (size_t)(gg*QT + lt) * SRED_STRIDE;
#pragma unroll
        for (int i = 0; i < NI; i++) o[i] += r[i];
        L += r[16];
    }
    const float inv = 1.0f / L;
#pragma unroll
    for (int i = 0; i < NI; i++) o[i] *= inv;

    const float gam = gamma[0];
    const int c0 = g * 32;
#pragma unroll 4
    for (int c = c0; c < c0 + 32; c++) {
        const float4* w = (const float4*)(swo + c*NI);
        float4 wa = w[0], wb = w[1], wc4 = w[2], wd = w[3];
        float s = sbo[c];
        s += wa.x*o[0]  + wa.y*o[1]  + wa.z*o[2]  + wa.w*o[3];
        s += wb.x*o[4]  + wb.y*o[5]  + wb.z*o[6]  + wb.w*o[7];
        s += wc4.x*o[8] + wc4.y*o[9] + wc4.z*o[10]+ wc4.w*o[11];
        s += wd.x*o[12] + wd.y*o[13] + wd.z*o[14] + wd.w*o[15];
        const size_t oi = ((size_t)b*CH + c)*NN + n;
        out[oi] = gam*s + x[oi];     // residual, coalesced over lt
    }
}

// ---------------- launch ----------------
extern "C" void kernel_launch(void* const* d_in, const int* in_sizes, int n_in,
                              void* d_out, int out_size) {
    (void)in_sizes; (void)n_in; (void)out_size;
    const float* x     = (const float*)d_in[0];
    const float* Wq    = (const float*)d_in[1];
    const float* bq    = (const float*)d_in[2];
    const float* Wk    = (const float*)d_in[3];
    const float* bk    = (const float*)d_in[4];
    const float* Wv    = (const float*)d_in[5];
    const float* bv    = (const float*)d_in[6];
    const float* Wo    = (const float*)d_in[7];
    const float* bo    = (const float*)d_in[8];
    const float* gamma = (const float*)d_in[9];
    float* out = (float*)d_out;

    cudaFuncSetAttribute(attn_kernel, cudaFuncAttributeMaxDynamicSharedMemorySize, SMEM_BYTES);

    qkv_kernel<<<dim3((BATCH*NN + 255)/256, 3), 256>>>(x, Wq, bq, Wk, bk, Wv, bv);
    attn_kernel<<<dim3(NN/QT, BATCH), THREADS, SMEM_BYTES>>>(x, Wo, bo, gamma, out);
}

// round 4
// speedup vs baseline: 1.2116x; 1.2116x over previous
#include <cuda_runtime.h>
#include <cstdint>
#include <cstddef>

// Problem constants (fixed shapes from reference)
#define BATCH 2
#define CH    128
#define NI    16            // inter channels
#define DD    16
#define HH    24
#define WW    24
#define NN    (DD*HH*WW)    // 9216 voxels
#define LOG2E 1.4426950408889634f

#define QT      128         // queries per block
#define KT      128         // keys per smem tile
#define GR      8           // key groups per block
#define LANES   64          // query lanes per group (each owns 2 queries)
#define THREADS (GR*LANES)  // 512
#define NTILES  (NN/KT)     // 72  -> 9 tiles per group

typedef unsigned long long u64;

// scratch: q (pre-scaled by log2e), k, v, each [B][N][16] row-major per voxel
__device__ float g_qkv[3][BATCH*NN*NI];

// ---------------- f32x2 helpers (FFMA2/FADD2: 2x fp32 throughput, PTX-only) ----
__device__ __forceinline__ u64 ffma2(u64 a, u64 b, u64 c) {
    u64 d;
    asm("fma.rn.f32x2 %0, %1, %2, %3;" : "=l"(d) : "l"(a), "l"(b), "l"(c));
    return d;
}
__device__ __forceinline__ u64 add2(u64 a, u64 b) {
    u64 d; asm("add.rn.f32x2 %0, %1, %2;" : "=l"(d) : "l"(a), "l"(b)); return d;
}
__device__ __forceinline__ u64 pack2(float x, float y) {
    u64 r; asm("mov.b64 %0, {%1, %2};" : "=l"(r) : "f"(x), "f"(y)); return r;
}
__device__ __forceinline__ float2 unpack2(u64 a) {
    float2 r; asm("mov.b64 {%0, %1}, %2;" : "=f"(r.x), "=f"(r.y) : "l"(a)); return r;
}
__device__ __forceinline__ float ex2f(float x) {
    float r; asm("ex2.approx.f32 %0, %1;" : "=f"(r) : "f"(x)); return r;
}

// ---------------- Kernel 1: QKV projection (1x1x1 conv) ------------------------
__global__ void qkv_kernel(const float* __restrict__ x,
                           const float* __restrict__ Wq, const float* __restrict__ bq,
                           const float* __restrict__ Wk, const float* __restrict__ bk,
                           const float* __restrict__ Wv, const float* __restrict__ bv) {
    __shared__ float sw[CH*NI];   // sw[c*16+i] = W[i][c]
    __shared__ float sb[NI];

    const int which = blockIdx.y;
    const float* W   = (which == 0) ? Wq : (which == 1) ? Wk : Wv;
    const float* bia = (which == 0) ? bq : (which == 1) ? bk : bv;

    for (int t = threadIdx.x; t < CH*NI; t += blockDim.x) {
        int c = t >> 4, i = t & 15;
        sw[t] = W[i*CH + c];
    }
    if (threadIdx.x < NI) sb[threadIdx.x] = bia[threadIdx.x];
    __syncthreads();

    const int idx = blockIdx.x * blockDim.x + threadIdx.x;   // b*N + n
    if (idx >= BATCH*NN) return;
    const int b = idx / NN;
    const int n = idx - b*NN;

    float acc[NI];
#pragma unroll
    for (int i = 0; i < NI; i++) acc[i] = sb[i];

    const float* xp = x + (size_t)b*CH*NN + n;
#pragma unroll 4
    for (int c = 0; c < CH; c++) {
        float xv = xp[(size_t)c*NN];
        const float4* wr = (const float4*)(sw + c*NI);
        float4 wa = wr[0], wb = wr[1], wc4 = wr[2], wd = wr[3];
        acc[0]  += wa.x*xv;  acc[1]  += wa.y*xv;  acc[2]  += wa.z*xv;  acc[3]  += wa.w*xv;
        acc[4]  += wb.x*xv;  acc[5]  += wb.y*xv;  acc[6]  += wb.z*xv;  acc[7]  += wb.w*xv;
        acc[8]  += wc4.x*xv; acc[9]  += wc4.y*xv; acc[10] += wc4.z*xv; acc[11] += wc4.w*xv;
        acc[12] += wd.x*xv;  acc[13] += wd.y*xv;  acc[14] += wd.z*xv;  acc[15] += wd.w*xv;
    }

    const float scale = (which == 0) ? LOG2E : 1.0f;
    float4* dst = (float4*)(g_qkv[which] + (size_t)idx*NI);
    dst[0] = make_float4(acc[0]*scale,  acc[1]*scale,  acc[2]*scale,  acc[3]*scale);
    dst[1] = make_float4(acc[4]*scale,  acc[5]*scale,  acc[6]*scale,  acc[7]*scale);
    dst[2] = make_float4(acc[8]*scale,  acc[9]*scale,  acc[10]*scale, acc[11]*scale);
    dst[3] = make_float4(acc[12]*scale, acc[13]*scale, acc[14]*scale, acc[15]*scale);
}

// ---------------- Kernel 2: streaming attention + out-proj + residual ----------
// 512 threads = 8 key-groups x 64 query-lanes; each thread owns 2 queries
// (lt and lt+64) -> k/v broadcast loads amortized over 2 queries (halves the
// LDS-crossbar demand that bound round 1). Group-private tiles + named
// barriers decouple groups. No max-subtraction (logits bounded << 88) ->
// partials additive across groups.
#define SRED_STRIDE 17
#define SMEM_FLOATS (GR*KT*NI + GR*KT*NI + CH*NI + CH + GR*QT*SRED_STRIDE)
#define SMEM_BYTES  (SMEM_FLOATS * 4)

__global__ void __launch_bounds__(THREADS, 1)
attn_kernel(const float* __restrict__ x,
            const float* __restrict__ Wo, const float* __restrict__ bo,
            const float* __restrict__ gamma, float* __restrict__ out) {
    extern __shared__ float smem[];
    float* kbuf = smem;                       // GR*KT*NI
    float* vbuf = kbuf + GR*KT*NI;            // GR*KT*NI
    float* swo  = vbuf + GR*KT*NI;            // CH*NI
    float* sbo  = swo + CH*NI;                // CH
    float* sred = sbo + CH;                   // GR*QT*17

    const int tid = threadIdx.x;
    const int g   = tid >> 6;        // key group 0..7
    const int lt  = tid & 63;        // query lane within group
    const int b   = blockIdx.y;
    const int q0  = blockIdx.x * QT;
    const int n0  = q0 + lt;         // query A
    const int n1  = n0 + 64;         // query B

    for (int t = tid; t < CH*NI; t += THREADS) swo[t] = Wo[t];
    if (tid < CH) sbo[tid] = bo[tid];

    // two query vectors (already * log2e), each 8x f32x2
    u64 qa[8], qb[8];
    {
        const ulonglong2* qp = (const ulonglong2*)(g_qkv[0] + (size_t)(b*NN + n0)*NI);
#pragma unroll
        for (int j = 0; j < 4; j++) { ulonglong2 t2 = qp[j]; qa[2*j] = t2.x; qa[2*j+1] = t2.y; }
        const ulonglong2* qp2 = (const ulonglong2*)(g_qkv[0] + (size_t)(b*NN + n1)*NI);
#pragma unroll
        for (int j = 0; j < 4; j++) { ulonglong2 t2 = qp2[j]; qb[2*j] = t2.x; qb[2*j+1] = t2.y; }
    }

    u64 aa[8], ab[8];
#pragma unroll
    for (int j = 0; j < 8; j++) { aa[j] = 0ull; ab[j] = 0ull; }
    u64 ls2 = 0ull;                 // packed (lsum0, lsum1)

    const float4* kg = (const float4*)(g_qkv[1] + (size_t)b*NN*NI);
    const float4* vg = (const float4*)(g_qkv[2] + (size_t)b*NN*NI);
    float4* myk = (float4*)(kbuf + g*KT*NI);
    float4* myv = (float4*)(vbuf + g*KT*NI);
    const u64* krow = (const u64*)(kbuf + g*KT*NI);
    const u64* vrow = (const u64*)(vbuf + g*KT*NI);

    for (int t = g; t < NTILES; t += GR) {     // 9 tiles per group
        const int m0 = t * KT;
        asm volatile("bar.sync %0, %1;" :: "r"(g+1), "r"(LANES) : "memory");
#pragma unroll
        for (int j = 0; j < 8; j++) {           // 1024 float4 per tile / 64 threads
            int e = lt + j*64;
            myk[e] = kg[(size_t)m0*4 + e];
            myv[e] = vg[(size_t)m0*4 + e];
        }
        asm volatile("bar.sync %0, %1;" :: "r"(g+1), "r"(LANES) : "memory");

#pragma unroll 2
        for (int m = 0; m < KT; m++) {
            const ulonglong2* km = (const ulonglong2*)(krow + (size_t)m*8);
            ulonglong2 ka = km[0], kb = km[1], kc = km[2], kd = km[3];
            u64 d0 = 0ull, d1 = 0ull, e0 = 0ull, e1 = 0ull;
            d0 = ffma2(qa[0], ka.x, d0);  d1 = ffma2(qa[1], ka.y, d1);
            e0 = ffma2(qb[0], ka.x, e0);  e1 = ffma2(qb[1], ka.y, e1);
            d0 = ffma2(qa[2], kb.x, d0);  d1 = ffma2(qa[3], kb.y, d1);
            e0 = ffma2(qb[2], kb.x, e0);  e1 = ffma2(qb[3], kb.y, e1);
            d0 = ffma2(qa[4], kc.x, d0);  d1 = ffma2(qa[5], kc.y, d1);
            e0 = ffma2(qb[4], kc.x, e0);  e1 = ffma2(qb[5], kc.y, e1);
            d0 = ffma2(qa[6], kd.x, d0);  d1 = ffma2(qa[7], kd.y, d1);
            e0 = ffma2(qb[6], kd.x, e0);  e1 = ffma2(qb[7], kd.y, e1);
            u64 da = add2(d0, d1);
            u64 db = add2(e0, e1);
            float2 fa = unpack2(da), fb = unpack2(db);
            float s0 = fa.x + fa.y;
            float s1 = fb.x + fb.y;
            float p0 = ex2f(s0);
            float p1 = ex2f(s1);
            ls2 = add2(ls2, pack2(p0, p1));
            u64 pp0 = pack2(p0, p0);
            u64 pp1 = pack2(p1, p1);
            const ulonglong2* vm = (const ulonglong2*)(vrow + (size_t)m*8);
            ulonglong2 va = vm[0], vb = vm[1], vc = vm[2], vd = vm[3];
            aa[0] = ffma2(pp0, va.x, aa[0]);  aa[1] = ffma2(pp0, va.y, aa[1]);
            ab[0] = ffma2(pp1, va.x, ab[0]);  ab[1] = ffma2(pp1, va.y, ab[1]);
            aa[2] = ffma2(pp0, vb.x, aa[2]);  aa[3] = ffma2(pp0, vb.y, aa[3]);
            ab[2] = ffma2(pp1, vb.x, ab[2]);  ab[3] = ffma2(pp1, vb.y, ab[3]);
            aa[4] = ffma2(pp0, vc.x, aa[4]);  aa[5] = ffma2(pp0, vc.y, aa[5]);
            ab[4] = ffma2(pp1, vc.x, ab[4]);  ab[5] = ffma2(pp1, vc.y, ab[5]);
            aa[6] = ffma2(pp0, vd.x, aa[6]);  aa[7] = ffma2(pp0, vd.y, aa[7]);
            ab[6] = ffma2(pp1, vd.x, ab[6]);  ab[7] = ffma2(pp1, vd.y, ab[7]);
        }
    }

    // write per-group partials for both queries (additive: no running max)
    {
        float2 ls = unpack2(ls2);
        float* pr = sred + (size_t)(g*QT + lt) * SRED_STRIDE;
#pragma unroll
        for (int j = 0; j < 8; j++) {
            float2 e = unpack2(aa[j]);
            pr[2*j] = e.x; pr[2*j+1] = e.y;
        }
        pr[16] = ls.x;
        float* pr2 = sred + (size_t)(g*QT + lt + 64) * SRED_STRIDE;
#pragma unroll
        for (int j = 0; j < 8; j++) {
            float2 e = unpack2(ab[j]);
            pr2[2*j] = e.x; pr2[2*j+1] = e.y;
        }
        pr2[16] = ls.y;
    }
    __syncthreads();

    // merge 8 partials; thread: query (tid&127), channels [(tid>>7)*32, +32)
    const int qe = tid & 127;
    const int ce = tid >> 7;         // 0..3
    float o[NI]; float L = 0.0f;
#pragma unroll
    for (int i = 0; i < NI; i++) o[i] = 0.0f;
#pragma unroll
    for (int gg = 0; gg < GR; gg++) {
        const float* r = sred + (size_t)(gg*QT + qe) * SRED_STRIDE;
#pragma unroll
        for (int i = 0; i < NI; i++) o[i] += r[i];
        L += r[16];
    }
    const float inv = 1.0f / L;
#pragma unroll
    for (int i = 0; i < NI; i++) o[i] *= inv;

    const float gam = gamma[0];
    const int n = q0 + qe;
    const int c0 = ce * 32;
#pragma unroll 4
    for (int c = c0; c < c0 + 32; c++) {
        const float4* w = (const float4*)(swo + c*NI);
        float4 wa = w[0], wb = w[1], wc4 = w[2], wd = w[3];
        float s = sbo[c];
        s += wa.x*o[0]  + wa.y*o[1]  + wa.z*o[2]  + wa.w*o[3];
        s += wb.x*o[4]  + wb.y*o[5]  + wb.z*o[6]  + wb.w*o[7];
        s += wc4.x*o[8] + wc4.y*o[9] + wc4.z*o[10]+ wc4.w*o[11];
        s += wd.x*o[12] + wd.y*o[13] + wd.z*o[14] + wd.w*o[15];
        const size_t oi = ((size_t)b*CH + c)*NN + n;
        out[oi] = gam*s + x[oi];     // residual, coalesced over qe
    }
}

// ---------------- launch ----------------
extern "C" void kernel_launch(void* const* d_in, const int* in_sizes, int n_in,
                              void* d_out, int out_size) {
    (void)in_sizes; (void)n_in; (void)out_size;
    const float* x     = (const float*)d_in[0];
    const float* Wq    = (const float*)d_in[1];
    const float* bq    = (const float*)d_in[2];
    const float* Wk    = (const float*)d_in[3];
    const float* bk    = (const float*)d_in[4];
    const float* Wv    = (const float*)d_in[5];
    const float* bv    = (const float*)d_in[6];
    const float* Wo    = (const float*)d_in[7];
    const float* bo    = (const float*)d_in[8];
    const float* gamma = (const float*)d_in[9];
    float* out = (float*)d_out;

    cudaFuncSetAttribute(attn_kernel, cudaFuncAttributeMaxDynamicSharedMemorySize, SMEM_BYTES);

    qkv_kernel<<<dim3((BATCH*NN + 255)/256, 3), 256>>>(x, Wq, bq, Wk, bk, Wv, bv);
    attn_kernel<<<dim3(NN/QT, BATCH), THREADS, SMEM_BYTES>>>(x, Wo, bo, gamma, out);
}